// round 2
// baseline (speedup 1.0000x reference)
#include <cuda_runtime.h>
#include <math.h>

#define HEADS 8
#define HW 64
#define D 32
#define NTOK 4096
#define DIMX 256
#define INCDIM 768

// ---------------- scratch (static device globals; no allocation) -------------
__device__ float g_Q[HEADS * NTOK * D];                 // 4 MB
__device__ float g_K[HEADS * NTOK * D];                 // 4 MB
__device__ float g_V[HEADS * NTOK * D];                 // 4 MB
__device__ float g_U[(size_t)HEADS * HW * HW * D * D];  // 134 MB row-cumsum of k (x) v
__device__ float g_Kc[HEADS * HW * HW * D];             // 4 MB row-cumsum of k
__device__ float g_Cat[(size_t)NTOK * INCDIM];          // 12.6 MB window-output concat

// ---------------- packed fp32x2 FMA (exact fp32, 2x issue density) -----------
__device__ __forceinline__ void ffma2(float2& d, float2 a, float2 b) {
    asm("fma.rn.f32x2 %0, %1, %2, %0;"
        : "+l"(*reinterpret_cast<unsigned long long*>(&d))
        : "l"(*reinterpret_cast<unsigned long long*>(&a)),
          "l"(*reinterpret_cast<unsigned long long*>(&b)));
}

// ---------------- shared GEMM mainloop: 128x64 tile, BK=32, 8x4/thread -------
// As[kk][m] transposed, Bs[kk][n]. 256 threads. acc2[i2][j]: rows paired.
#define GBM 128
#define GBN 64
#define GBK 32

__device__ __forceinline__ void gemm_mainloop(
    const float* __restrict__ A, int lda,
    const float* __restrict__ B, int ldb,
    int K, int row0, int col0,
    float* As, float* Bs, float2 acc[4][4]) {
    const int tid = threadIdx.x;
    const int tx = tid & 15, ty = tid >> 4;
    for (int k0 = 0; k0 < K; k0 += GBK) {
#pragma unroll
        for (int i = 0; i < 4; i++) {
            int idx = tid + i * 256;
            int m = idx & 127, kq = idx >> 7;            // kq 0..7
            float4 av = *(const float4*)&A[(size_t)(row0 + m) * lda + k0 + kq * 4];
            As[(kq * 4 + 0) * GBM + m] = av.x;
            As[(kq * 4 + 1) * GBM + m] = av.y;
            As[(kq * 4 + 2) * GBM + m] = av.z;
            As[(kq * 4 + 3) * GBM + m] = av.w;
        }
#pragma unroll
        for (int i = 0; i < 2; i++) {
            int idx = tid + i * 256;
            int n4 = idx & 15, kk = idx >> 4;            // kk 0..31
            *(float4*)&Bs[kk * GBN + n4 * 4] =
                *(const float4*)&B[(size_t)(k0 + kk) * ldb + col0 + n4 * 4];
        }
        __syncthreads();
#pragma unroll
        for (int kk = 0; kk < GBK; kk++) {
            float4 alo = *(float4*)&As[kk * GBM + ty * 8];
            float4 ahi = *(float4*)&As[kk * GBM + ty * 8 + 4];
            float4 bv  = *(float4*)&Bs[kk * GBN + tx * 4];
            float2 a2[4] = {{alo.x, alo.y}, {alo.z, alo.w}, {ahi.x, ahi.y}, {ahi.z, ahi.w}};
            float2 b2[4] = {{bv.x, bv.x}, {bv.y, bv.y}, {bv.z, bv.z}, {bv.w, bv.w}};
#pragma unroll
            for (int i2 = 0; i2 < 4; i2++)
#pragma unroll
                for (int j = 0; j < 4; j++) ffma2(acc[i2][j], a2[i2], b2[j]);
        }
        __syncthreads();
    }
}

// ---------------- Kernel 1: fused QKV GEMM + ELU epilogue --------------------
__global__ __launch_bounds__(256) void k_qkv(const float* __restrict__ x,
                                             const float* __restrict__ wq,
                                             const float* __restrict__ wk,
                                             const float* __restrict__ wv) {
    __shared__ float As[GBK * GBM];
    __shared__ float Bs[GBK * GBN];
    const int row0 = blockIdx.x * GBM;
    const int col0 = blockIdx.y * GBN;       // 0..767
    const int part = col0 >> 8;              // 0=q 1=k 2=v
    const int wc0  = col0 & 255;
    const float* W = (part == 0) ? wq : (part == 1) ? wk : wv;
    float2 acc[4][4] = {};
    gemm_mainloop(x, DIMX, W, DIMX, DIMX, row0, wc0, As, Bs, acc);

    float* dst = (part == 0) ? g_Q : (part == 1) ? g_K : g_V;
    const int tx = threadIdx.x & 15, ty = threadIdx.x >> 4;
#pragma unroll
    for (int i2 = 0; i2 < 4; i2++) {
#pragma unroll
        for (int l = 0; l < 2; l++) {
            int n = row0 + ty * 8 + i2 * 2 + l;
#pragma unroll
            for (int j = 0; j < 4; j++) {
                int cc = wc0 + tx * 4 + j;
                int h = cc >> 5, e = cc & 31;
                float val = l ? acc[i2][j].y : acc[i2][j].x;
                if (part < 2)
                    val = (val > 0.f) ? (val + 1.000001f) : (expf(val) + 1e-6f);
                dst[((size_t)(h * NTOK + n)) * D + e] = val;
            }
        }
    }
}

// ---------------- Kernel 2: row-direction cumsums ----------------------------
__global__ __launch_bounds__(256) void k_integral() {
    const int j = blockIdx.x;
    const int h = blockIdx.y;
    __shared__ float ksh[HW * D];
    __shared__ float vsh[HW * D];
    const int tid = threadIdx.x;
#pragma unroll
    for (int r = 0; r < 8; r++) {
        int l = tid + r * 256;
        int i = l >> 5, a = l & 31;
        size_t gi = ((size_t)(h * NTOK + i * HW + j)) * D + a;
        ksh[l] = g_K[gi];
        vsh[l] = g_V[gi];
    }
    __syncthreads();
    const int a = tid >> 3;
    const int b = (tid & 7) * 4;
    float4 acc = make_float4(0.f, 0.f, 0.f, 0.f);
    float kacc = 0.f;
    for (int i = 0; i < HW; i++) {
        float kv = ksh[i * D + a];
        float4 vv = *(const float4*)&vsh[i * D + b];
        acc.x += kv * vv.x; acc.y += kv * vv.y; acc.z += kv * vv.z; acc.w += kv * vv.w;
        *(float4*)&g_U[(((size_t)(h * HW + i)) * HW + j) * (D * D) + tid * 4] = acc;
        if (tid < 32) {
            kacc += ksh[i * D + tid];
            g_Kc[((h * HW + i) * HW + j) * D + tid] = kacc;
        }
    }
}

// ---------------- Kernel 3: windowed linear attention sweep ------------------
// block = (ii, window, head). One barrier per sweep step via double-buffered
// prefix matrix; next step's band loads prefetched before the barrier.
__global__ __launch_bounds__(256) void k_attn() {
    const int ii = blockIdx.x;
    const int win = blockIdx.y;
    const int h = blockIdx.z;
    const int r = (win == 0) ? 32 : (win == 1) ? 16 : 8;

    __shared__ float qsh[HW * D];
    __shared__ float Msh[2][D * D];
    __shared__ float numsh[HW * D];
    __shared__ float densh[HW];
    __shared__ float pksh[2][D];

    const int tid = threadIdx.x;
    const int warp = tid >> 5, lane = tid & 31;

#pragma unroll
    for (int rr = 0; rr < 8; rr++) {
        int l = tid + rr * 256;
        qsh[l] = g_Q[((size_t)(h * NTOK + ii * HW)) * D + l];
        numsh[l] = 0.f;
    }
    *(float4*)&Msh[1][tid * 4] = make_float4(0.f, 0.f, 0.f, 0.f);
    if (tid < 64) densh[tid] = 0.f;
    if (tid < 32) pksh[1][tid] = 0.f;

    const int x2 = min(ii + r, HW - 1);
    const int xl = ii - r - 1;
    const bool hasl = (xl >= 0);
    const float* Uh = g_U + ((size_t)(h * HW + x2)) * HW * (D * D);
    const float* Ul = g_U + ((size_t)(h * HW + max(xl, 0))) * HW * (D * D);
    const float* Kh = g_Kc + (h * HW + x2) * HW * D;
    const float* Kl = g_Kc + (h * HW + max(xl, 0)) * HW * D;

    // prefetch step j=0
    float4 d = *(const float4*)&Uh[tid * 4];
    float kd = (tid < 32) ? Kh[tid] : 0.f;
    if (hasl) {
        float4 dl = *(const float4*)&Ul[tid * 4];
        d.x -= dl.x; d.y -= dl.y; d.z -= dl.z; d.w -= dl.w;
        if (tid < 32) kd -= Kl[tid];
    }
    __syncthreads();    // init writes visible

    for (int j = 0; j < HW; j++) {
        const int cur = j & 1, prev = cur ^ 1;
        // update prefix into current buffer
        float4 m = *(float4*)&Msh[prev][tid * 4];
        m.x += d.x; m.y += d.y; m.z += d.z; m.w += d.w;
        *(float4*)&Msh[cur][tid * 4] = m;
        if (tid < 32) pksh[cur][tid] = pksh[prev][tid] + kd;
        // prefetch step j+1 (hidden under barrier + events)
        if (j < HW - 1) {
            size_t off = (size_t)(j + 1) * (D * D) + tid * 4;
            d = *(const float4*)&Uh[off];
            kd = (tid < 32) ? Kh[(j + 1) * D + tid] : 0.f;
            if (hasl) {
                float4 dl = *(const float4*)&Ul[off];
                d.x -= dl.x; d.y -= dl.y; d.z -= dl.z; d.w -= dl.w;
                if (tid < 32) kd -= Kl[(j + 1) * D + tid];
            }
        }
        __syncthreads();   // P(y=j) ready; also fences step j-1's event reads

        // events: +1 at y2(jj)==j ; -1 at y1(jj)-1==j
        const int nplus = (j == HW - 1) ? (r + 1) : ((j >= r) ? 1 : 0);
        const int jjp0  = (j == HW - 1) ? (HW - 1 - r) : (j - r);
        const int hasminus = (j + r + 1 <= HW - 1) ? 1 : 0;
        const int nev = nplus + hasminus;
        for (int e = warp; e < nev; e += 8) {
            int jj; float sgn;
            if (e < nplus) { jj = jjp0 + e; sgn = 1.f; }
            else           { jj = j + r + 1; sgn = -1.f; }
            const float* qrow = &qsh[jj * D];
            float rv = 0.f;
#pragma unroll
            for (int a = 0; a < 32; a++) rv += qrow[a] * Msh[cur][a * 32 + lane];
            numsh[jj * D + lane] += sgn * rv;
            float p = qrow[lane] * pksh[cur][lane];
#pragma unroll
            for (int off = 16; off; off >>= 1) p += __shfl_xor_sync(0xffffffffu, p, off);
            if (lane == 0) densh[jj] += sgn * p;
        }
    }
    __syncthreads();
#pragma unroll
    for (int rr = 0; rr < 8; rr++) {
        int l = tid + rr * 256;
        int jj = l >> 5, e = l & 31;
        float o = numsh[l] / (densh[jj] + 1e-6f);
        g_Cat[(size_t)(ii * HW + jj) * INCDIM + win * DIMX + h * D + e] = o;
    }
}

// ---------------- Kernel 4: output GEMM + bias -------------------------------
__global__ __launch_bounds__(256) void k_out(const float* __restrict__ wo,
                                             const float* __restrict__ bo,
                                             float* __restrict__ out) {
    __shared__ float As[GBK * GBM];
    __shared__ float Bs[GBK * GBN];
    const int row0 = blockIdx.x * GBM;
    const int col0 = blockIdx.y * GBN;      // 0..255
    float2 acc[4][4] = {};
    gemm_mainloop(g_Cat, INCDIM, wo, DIMX, INCDIM, row0, col0, As, Bs, acc);

    const int tx = threadIdx.x & 15, ty = threadIdx.x >> 4;
#pragma unroll
    for (int i2 = 0; i2 < 4; i2++) {
#pragma unroll
        for (int l = 0; l < 2; l++) {
            int n = row0 + ty * 8 + i2 * 2 + l;
#pragma unroll
            for (int j = 0; j < 4; j++) {
                int c = col0 + tx * 4 + j;
                float val = l ? acc[i2][j].y : acc[i2][j].x;
                out[(size_t)n * DIMX + c] = val + bo[c];
            }
        }
    }
}

// ---------------- launch -----------------------------------------------------
extern "C" void kernel_launch(void* const* d_in, const int* in_sizes, int n_in,
                              void* d_out, int out_size) {
    const float* x  = (const float*)d_in[0];
    const float* wq = (const float*)d_in[1];
    const float* wk = (const float*)d_in[2];
    const float* wv = (const float*)d_in[3];
    const float* wo = (const float*)d_in[4];
    const float* bo = (const float*)d_in[5];
    float* out = (float*)d_out;

    k_qkv<<<dim3(NTOK / GBM, INCDIM / GBN), 256>>>(x, wq, wk, wv);
    k_integral<<<dim3(HW, HEADS), 256>>>();
    k_attn<<<dim3(HW, 3, HEADS), 256>>>();
    k_out<<<dim3(NTOK / GBM, DIMX / GBN), 256>>>(wo, bo, out);
}